// round 2
// baseline (speedup 1.0000x reference)
#include <cuda_runtime.h>

#define C2 2048
#define TT 2176
#define SQ 132

typedef unsigned long long u64;

// ---------- packed f32x2 helpers ----------
__device__ __forceinline__ u64 pack2(float x) {
    u64 r;
    asm("mov.b64 %0, {%1, %1};" : "=l"(r) : "r"(__float_as_uint(x)));
    return r;
}
__device__ __forceinline__ void fma2(u64& d, u64 a, u64 b) {
    asm("fma.rn.f32x2 %0, %1, %2, %0;" : "+l"(d) : "l"(a), "l"(b));
}
__device__ __forceinline__ u64 mul2(u64 a, u64 b) {
    u64 r;
    asm("mul.rn.f32x2 %0, %1, %2;" : "=l"(r) : "l"(a), "l"(b));
    return r;
}
__device__ __forceinline__ float lo2(u64 v) { return __uint_as_float((unsigned)v); }
__device__ __forceinline__ float hi2(u64 v) { return __uint_as_float((unsigned)(v >> 32)); }

// ---------- device scratch (static: no runtime alloc) ----------
__device__ float g_Q[8 * 16 * 128 * 128];      // (B,H,T_NEW,D), pre-scaled
__device__ float g_attn[8 * 128 * 2048];       // (B,T_NEW,C)

// ---------- 1) KV cache copy-through ----------
__global__ void copy_past_kernel(const float4* __restrict__ Kp, const float4* __restrict__ Vp,
                                 float4* __restrict__ Ko, float4* __restrict__ Vo) {
    int idx = blockIdx.x * 256 + threadIdx.x;          // f4 index, 0..8388607
    int bh  = idx >> 16;                               // / (2048*128/4)
    int rem = idx & 65535;
    size_t dst = (size_t)bh * 69632 + rem;             // 2176*128/4 per (b,h)
    Ko[dst] = Kp[idx];
    Vo[dst] = Vp[idx];
}

// ---------- shared GEMM core: 128x128 tile, BK=16, 256 thr, 8x8 micro, f32x2 ----------
__device__ __forceinline__ void gemm_tile(const float* __restrict__ A,
                                          const float* __restrict__ W,
                                          int m0, int n0, u64 acc[8][4]) {
    __shared__ float As[16 * SQ];   // [k][m] (transposed)
    __shared__ float Bs[16 * SQ];   // [k][n]
    const int t  = threadIdx.x;
    const int tx = t & 15, ty = t >> 4;
    const int arow = t >> 1, ak = (t & 1) * 8;
    const int bk = t >> 4, bn = (t & 15) * 8;
    const float* Ap = A + (size_t)(m0 + arow) * C2 + ak;
    const float* Wp = W + (size_t)bk * C2 + n0 + bn;

    for (int k0 = 0; k0 < C2; k0 += 16) {
        float4 a0 = *(const float4*)(Ap + k0);
        float4 a1 = *(const float4*)(Ap + k0 + 4);
        float4 b0 = *(const float4*)(Wp + (size_t)k0 * C2);
        float4 b1 = *(const float4*)(Wp + (size_t)k0 * C2 + 4);
        __syncthreads();
        As[(ak + 0) * SQ + arow] = a0.x;
        As[(ak + 1) * SQ + arow] = a0.y;
        As[(ak + 2) * SQ + arow] = a0.z;
        As[(ak + 3) * SQ + arow] = a0.w;
        As[(ak + 4) * SQ + arow] = a1.x;
        As[(ak + 5) * SQ + arow] = a1.y;
        As[(ak + 6) * SQ + arow] = a1.z;
        As[(ak + 7) * SQ + arow] = a1.w;
        *(float4*)&Bs[bk * SQ + bn]     = b0;
        *(float4*)&Bs[bk * SQ + bn + 4] = b1;
        __syncthreads();
#pragma unroll
        for (int kk = 0; kk < 16; kk++) {
            const u64* bp = (const u64*)&Bs[kk * SQ + tx * 8];
            u64 q0 = bp[0], q1 = bp[1], q2 = bp[2], q3 = bp[3];
            float4 f0 = *(const float4*)&As[kk * SQ + ty * 8];
            float4 f1 = *(const float4*)&As[kk * SQ + ty * 8 + 4];
            float av[8] = {f0.x, f0.y, f0.z, f0.w, f1.x, f1.y, f1.z, f1.w};
#pragma unroll
            for (int i = 0; i < 8; i++) {
                u64 pa = pack2(av[i]);
                fma2(acc[i][0], pa, q0);
                fma2(acc[i][1], pa, q1);
                fma2(acc[i][2], pa, q2);
                fma2(acc[i][3], pa, q3);
            }
        }
    }
}

// ---------- 2) fused QKV projection ----------
__global__ __launch_bounds__(256) void qkv_kernel(
    const float* __restrict__ x,
    const float* __restrict__ Wq, const float* __restrict__ bq,
    const float* __restrict__ Wk, const float* __restrict__ bk,
    const float* __restrict__ Wv, const float* __restrict__ bv,
    float* __restrict__ Kout, float* __restrict__ Vout) {
    const int wsel = blockIdx.z;
    const float* W    = (wsel == 0) ? Wq : (wsel == 1 ? Wk : Wv);
    const float* bias = (wsel == 0) ? bq : (wsel == 1 ? bk : bv);
    const int m0 = blockIdx.y * 128, n0 = blockIdx.x * 128;

    u64 acc[8][4];
#pragma unroll
    for (int i = 0; i < 8; i++)
#pragma unroll
        for (int j = 0; j < 4; j++) acc[i][j] = 0ULL;

    gemm_tile(x, W, m0, n0, acc);

    const int t = threadIdx.x, tx = t & 15, ty = t >> 4;
    float4 bb0 = *(const float4*)(bias + n0 + tx * 8);
    float4 bb1 = *(const float4*)(bias + n0 + tx * 8 + 4);
    const float scale = (wsel == 0) ? 0.08838834764831845f : 1.0f;

    const int gn = n0 + tx * 8;
    const int h = gn >> 7, dc = gn & 127;
#pragma unroll
    for (int i = 0; i < 8; i++) {
        const int gr = m0 + ty * 8 + i;       // 0..1023
        const int b = gr >> 7, tq = gr & 127;
        float4 o0 = make_float4((lo2(acc[i][0]) + bb0.x) * scale,
                                (hi2(acc[i][0]) + bb0.y) * scale,
                                (lo2(acc[i][1]) + bb0.z) * scale,
                                (hi2(acc[i][1]) + bb0.w) * scale);
        float4 o1 = make_float4((lo2(acc[i][2]) + bb1.x) * scale,
                                (hi2(acc[i][2]) + bb1.y) * scale,
                                (lo2(acc[i][3]) + bb1.z) * scale,
                                (hi2(acc[i][3]) + bb1.w) * scale);
        float* dst;
        if (wsel == 0) {
            dst = g_Q + ((size_t)(b * 16 + h) * 128 + tq) * 128 + dc;
        } else {
            float* base = (wsel == 1) ? Kout : Vout;
            dst = base + ((size_t)(b * 16 + h) * TT + 2048 + tq) * 128 + dc;
        }
        *(float4*)dst       = o0;
        *(float4*)(dst + 4) = o1;
    }
}

// ---------- 3) flash attention: one CTA per (b,h) ----------
extern __shared__ float sm[];
__global__ __launch_bounds__(256) void attn_kernel(const float* __restrict__ Kc,
                                                   const float* __restrict__ Vc) {
    float* Qs   = sm;                    // [d][q] transposed, 128*SQ
    float* Ks   = Qs + 128 * SQ;         // [d][k] transposed; reused as Ps [q][k]
    float* Vs   = Ks + 128 * SQ;         // [k][c] natural
    float* red  = Vs + 128 * SQ;         // 128*16
    float* mrow = red + 128 * 16;        // 128
    float* lrow = mrow + 128;            // 128
    float* frow = lrow + 128;            // 128
    float* Ps   = Ks;

    const int bh = blockIdx.x;
    const int t = threadIdx.x, tx = t & 15, ty = t >> 4;

    // load Q transposed
    const float* Qg = g_Q + (size_t)bh * 128 * 128;
    for (int i = t; i < 128 * 32; i += 256) {
        int r = i >> 5, c4 = (i & 31) * 4;
        float4 qv = *(const float4*)&Qg[r * 128 + c4];
        Qs[(c4 + 0) * SQ + r] = qv.x;
        Qs[(c4 + 1) * SQ + r] = qv.y;
        Qs[(c4 + 2) * SQ + r] = qv.z;
        Qs[(c4 + 3) * SQ + r] = qv.w;
    }
    if (t < 128) { mrow[t] = -1e30f; lrow[t] = 0.f; }

    u64 o[8][4];
#pragma unroll
    for (int i = 0; i < 8; i++)
#pragma unroll
        for (int j = 0; j < 4; j++) o[i][j] = 0ULL;

    const float* Kg = Kc + (size_t)bh * TT * 128;
    const float* Vg = Vc + (size_t)bh * TT * 128;

    for (int kt = 0; kt < 17; kt++) {
        __syncthreads();   // previous Ps / Vs / red consumers done
        // K transposed -> Ks[d][k], V natural -> Vs[k][c]
        for (int i = t; i < 128 * 32; i += 256) {
            int r = i >> 5, c4 = (i & 31) * 4;
            float4 kv = *(const float4*)&Kg[(size_t)(kt * 128 + r) * 128 + c4];
            Ks[(c4 + 0) * SQ + r] = kv.x;
            Ks[(c4 + 1) * SQ + r] = kv.y;
            Ks[(c4 + 2) * SQ + r] = kv.z;
            Ks[(c4 + 3) * SQ + r] = kv.w;
            *(float4*)&Vs[r * SQ + c4] = *(const float4*)&Vg[(size_t)(kt * 128 + r) * 128 + c4];
        }
        __syncthreads();

        // S = Q K^T (Q pre-scaled)
        u64 s[8][4];
#pragma unroll
        for (int i = 0; i < 8; i++)
#pragma unroll
            for (int j = 0; j < 4; j++) s[i][j] = 0ULL;
#pragma unroll 2
        for (int d = 0; d < 128; d++) {
            const u64* bp = (const u64*)&Ks[d * SQ + tx * 8];
            u64 q0 = bp[0], q1 = bp[1], q2 = bp[2], q3 = bp[3];
            float4 f0 = *(const float4*)&Qs[d * SQ + ty * 8];
            float4 f1 = *(const float4*)&Qs[d * SQ + ty * 8 + 4];
            float av[8] = {f0.x, f0.y, f0.z, f0.w, f1.x, f1.y, f1.z, f1.w};
#pragma unroll
            for (int i = 0; i < 8; i++) {
                u64 pa = pack2(av[i]);
                fma2(s[i][0], pa, q0);
                fma2(s[i][1], pa, q1);
                fma2(s[i][2], pa, q2);
                fma2(s[i][3], pa, q3);
            }
        }

        const bool last = (kt == 16);
        // local row max (mask applied on the fly)
#pragma unroll
        for (int i = 0; i < 8; i++) {
            const int q = ty * 8 + i;
            float mx = -1e30f;
#pragma unroll
            for (int j = 0; j < 4; j++) {
                float vl = lo2(s[i][j]), vh = hi2(s[i][j]);
                if (last && (tx * 8 + 2 * j)     > q) vl = -1e30f;
                if (last && (tx * 8 + 2 * j + 1) > q) vh = -1e30f;
                mx = fmaxf(mx, fmaxf(vl, vh));
            }
            red[q * 16 + tx] = mx;
        }
        __syncthreads();
        if (t < 128) {
            float mx = red[t * 16];
#pragma unroll
            for (int u = 1; u < 16; u++) mx = fmaxf(mx, red[t * 16 + u]);
            float mnew = fmaxf(mrow[t], mx);
            float f = __expf(mrow[t] - mnew);
            frow[t] = f;
            lrow[t] *= f;
            mrow[t] = mnew;
        }
        __syncthreads();

        // P = exp(S - m); write P to smem; rescale O; partial row sums
#pragma unroll
        for (int i = 0; i < 8; i++) {
            const int q = ty * 8 + i;
            const float mq = mrow[q];
            const u64 pf = pack2(frow[q]);
            o[i][0] = mul2(o[i][0], pf);
            o[i][1] = mul2(o[i][1], pf);
            o[i][2] = mul2(o[i][2], pf);
            o[i][3] = mul2(o[i][3], pf);
            float ssum = 0.f;
#pragma unroll
            for (int j = 0; j < 4; j++) {
                float vl = lo2(s[i][j]), vh = hi2(s[i][j]);
                if (last && (tx * 8 + 2 * j)     > q) vl = -1e30f;
                if (last && (tx * 8 + 2 * j + 1) > q) vh = -1e30f;
                float pl = __expf(vl - mq), ph = __expf(vh - mq);
                Ps[q * SQ + tx * 8 + 2 * j]     = pl;
                Ps[q * SQ + tx * 8 + 2 * j + 1] = ph;
                ssum += pl + ph;
            }
            red[q * 16 + tx] = ssum;
        }
        __syncthreads();
        if (t < 128) {
            float sacc = 0.f;
#pragma unroll
            for (int u = 0; u < 16; u++) sacc += red[t * 16 + u];
            lrow[t] += sacc;
        }

        // O += P V
#pragma unroll 2
        for (int k = 0; k < 128; k++) {
            const u64* vp = (const u64*)&Vs[k * SQ + tx * 8];
            u64 v0 = vp[0], v1 = vp[1], v2 = vp[2], v3 = vp[3];
#pragma unroll
            for (int i = 0; i < 8; i++) {
                u64 pa = pack2(Ps[(ty * 8 + i) * SQ + k]);
                fma2(o[i][0], pa, v0);
                fma2(o[i][1], pa, v1);
                fma2(o[i][2], pa, v2);
                fma2(o[i][3], pa, v3);
            }
        }
    }
    __syncthreads();

    const int b = bh >> 4, h = bh & 15;
#pragma unroll
    for (int i = 0; i < 8; i++) {
        const int q = ty * 8 + i;
        const float inv = 1.f / lrow[q];
        float4 o0 = make_float4(lo2(o[i][0]) * inv, hi2(o[i][0]) * inv,
                                lo2(o[i][1]) * inv, hi2(o[i][1]) * inv);
        float4 o1 = make_float4(lo2(o[i][2]) * inv, hi2(o[i][2]) * inv,
                                lo2(o[i][3]) * inv, hi2(o[i][3]) * inv);
        float* dst = g_attn + ((size_t)(b * 128 + q)) * C2 + h * 128 + tx * 8;
        *(float4*)dst       = o0;
        *(float4*)(dst + 4) = o1;
    }
}

// ---------- 4) output projection ----------
__global__ __launch_bounds__(256) void proj_kernel(const float* __restrict__ Wo,
                                                   const float* __restrict__ bo,
                                                   float* __restrict__ out) {
    const int m0 = blockIdx.y * 128, n0 = blockIdx.x * 128;
    u64 acc[8][4];
#pragma unroll
    for (int i = 0; i < 8; i++)
#pragma unroll
        for (int j = 0; j < 4; j++) acc[i][j] = 0ULL;

    gemm_tile(g_attn, Wo, m0, n0, acc);

    const int t = threadIdx.x, tx = t & 15, ty = t >> 4;
    float4 bb0 = *(const float4*)(bo + n0 + tx * 8);
    float4 bb1 = *(const float4*)(bo + n0 + tx * 8 + 4);
#pragma unroll
    for (int i = 0; i < 8; i++) {
        const int gr = m0 + ty * 8 + i;
        float4 o0 = make_float4(lo2(acc[i][0]) + bb0.x, hi2(acc[i][0]) + bb0.y,
                                lo2(acc[i][1]) + bb0.z, hi2(acc[i][1]) + bb0.w);
        float4 o1 = make_float4(lo2(acc[i][2]) + bb1.x, hi2(acc[i][2]) + bb1.y,
                                lo2(acc[i][3]) + bb1.z, hi2(acc[i][3]) + bb1.w);
        float* dst = out + (size_t)gr * C2 + n0 + tx * 8;
        *(float4*)dst       = o0;
        *(float4*)(dst + 4) = o1;
    }
}

// ---------- launch ----------
extern "C" void kernel_launch(void* const* d_in, const int* in_sizes, int n_in,
                              void* d_out, int out_size) {
    const float* x  = (const float*)d_in[0];
    const float* Kp = (const float*)d_in[1];
    const float* Vp = (const float*)d_in[2];
    const float* Wq = (const float*)d_in[3];
    const float* bq = (const float*)d_in[4];
    const float* Wk = (const float*)d_in[5];
    const float* bk = (const float*)d_in[6];
    const float* Wv = (const float*)d_in[7];
    const float* bv = (const float*)d_in[8];
    const float* Wo = (const float*)d_in[9];
    const float* bo = (const float*)d_in[10];

    float* out  = (float*)d_out;
    float* Kout = (float*)d_out + 2097152;                 // B*T_NEW*C
    float* Vout = (float*)d_out + 2097152 + 35651584;      // + B*H*TT*D

    // 1) copy past KV into cache
    copy_past_kernel<<<32768, 256>>>((const float4*)Kp, (const float4*)Vp,
                                     (float4*)Kout, (float4*)Vout);
    // 2) QKV projection
    qkv_kernel<<<dim3(16, 8, 3), 256>>>(x, Wq, bq, Wk, bk, Wv, bv, Kout, Vout);
    // 3) attention
    const int smem_bytes = (3 * 128 * SQ + 128 * 16 + 3 * 128) * (int)sizeof(float);
    cudaFuncSetAttribute(attn_kernel, cudaFuncAttributeMaxDynamicSharedMemorySize, smem_bytes);
    attn_kernel<<<128, 256, smem_bytes>>>(Kout, Vout);
    // 4) output projection
    proj_kernel<<<dim3(16, 8), 256>>>(Wo, bo, out);
}

// round 3
// speedup vs baseline: 2.6091x; 2.6091x over previous
#include <cuda_runtime.h>
#include <cstdint>

#define TT 2176

typedef unsigned int u32;

// ---------------- device scratch ----------------
__device__ float g_Q[8 * 16 * 128 * 128];      // (B,H,128,128) pre-scaled Q
__device__ float g_attn[8 * 128 * 2048];       // (B,T_NEW,C) attention output

// ---------------- helpers ----------------
__device__ __forceinline__ u32 cvt_tf32(float f) {
    u32 r; asm("cvt.rna.tf32.f32 %0, %1;" : "=r"(r) : "f"(f)); return r;
}
__device__ __forceinline__ u32 smem_u32(const void* p) {
    return (u32)__cvta_generic_to_shared(p);
}
__device__ __forceinline__ void ldsm_x4(u32 a, u32& r0, u32& r1, u32& r2, u32& r3) {
    asm volatile("ldmatrix.sync.aligned.m8n8.x4.shared.b16 {%0,%1,%2,%3}, [%4];"
                 : "=r"(r0), "=r"(r1), "=r"(r2), "=r"(r3) : "r"(a));
}
__device__ __forceinline__ void ldsm_x2(u32 a, u32& r0, u32& r1) {
    asm volatile("ldmatrix.sync.aligned.m8n8.x2.shared.b16 {%0,%1}, [%2];"
                 : "=r"(r0), "=r"(r1) : "r"(a));
}
__device__ __forceinline__ void mma8(float c[4], const u32 a[4], const u32 b[2]) {
    asm volatile("mma.sync.aligned.m16n8k8.row.col.f32.tf32.tf32.f32 "
                 "{%0,%1,%2,%3}, {%4,%5,%6,%7}, {%8,%9}, {%0,%1,%2,%3};"
                 : "+f"(c[0]), "+f"(c[1]), "+f"(c[2]), "+f"(c[3])
                 : "r"(a[0]), "r"(a[1]), "r"(a[2]), "r"(a[3]), "r"(b[0]), "r"(b[1]));
}

// ---------------- 1) KV cache copy-through ----------------
__global__ void copy_past_kernel(const float4* __restrict__ Kp, const float4* __restrict__ Vp,
                                 float4* __restrict__ Ko, float4* __restrict__ Vo) {
    int idx = blockIdx.x * 256 + threadIdx.x;          // 0..8388607 f4 units
    int bh  = idx >> 16;
    int rem = idx & 65535;
    size_t dst = (size_t)bh * 69632 + rem;             // 2176*128/4 per (b,h)
    Ko[dst] = Kp[idx];
    Vo[dst] = Vp[idx];
}

// ---------------- shared tf32 GEMM core: 128x128 tile, BK=32 ----------------
// As [128][36] row-major (tf32 bits), Bs [32][132] row-major (tf32 bits)
__device__ __forceinline__ void gemm_core(const float* __restrict__ A, const float* __restrict__ W,
                                          int m0, int n0, float c[4][4][4],
                                          float* As, float* Bs) {
    const int t = threadIdx.x, lane = t & 31, wid = t >> 5;
    const int ar = t >> 3, ac = (t & 7) * 4;           // A loader: rows t/8 (+32j), cols 4*(t%8)
    const int br = t >> 5, bc = (t & 31) * 4;          // B loader: rows t/32 (+8j), cols 4*(t%32)
    const int wm = (wid >> 2) * 64, wn = (wid & 3) * 32;
    const int g = lane & 3, nrow = lane >> 2;
    const u32 abase = smem_u32(As) +
        (((lane & 7) + ((lane >> 3) & 1) * 8) * 36 + (lane >> 4) * 4) * 4;

    for (int k0 = 0; k0 < 2048; k0 += 32) {
        float4 aL[4], bL[4];
#pragma unroll
        for (int j = 0; j < 4; j++)
            aL[j] = *(const float4*)(A + (size_t)(m0 + ar + 32 * j) * 2048 + k0 + ac);
#pragma unroll
        for (int j = 0; j < 4; j++)
            bL[j] = *(const float4*)(W + (size_t)(k0 + br + 8 * j) * 2048 + n0 + bc);
        __syncthreads();
#pragma unroll
        for (int j = 0; j < 4; j++) {
            uint4 ua = make_uint4(cvt_tf32(aL[j].x), cvt_tf32(aL[j].y),
                                  cvt_tf32(aL[j].z), cvt_tf32(aL[j].w));
            *(uint4*)(As + (ar + 32 * j) * 36 + ac) = ua;
            uint4 ub = make_uint4(cvt_tf32(bL[j].x), cvt_tf32(bL[j].y),
                                  cvt_tf32(bL[j].z), cvt_tf32(bL[j].w));
            *(uint4*)(Bs + (br + 8 * j) * 132 + bc) = ub;
        }
        __syncthreads();
#pragma unroll
        for (int ks = 0; ks < 4; ks++) {
            u32 af[4][4];
#pragma unroll
            for (int mt = 0; mt < 4; mt++)
                ldsm_x4(abase + ((wm + mt * 16) * 36 + ks * 8) * 4,
                        af[mt][0], af[mt][1], af[mt][2], af[mt][3]);
            u32 bf[4][2];
#pragma unroll
            for (int nt = 0; nt < 4; nt++) {
                bf[nt][0] = __float_as_uint(Bs[(ks * 8 + g) * 132 + wn + nt * 8 + nrow]);
                bf[nt][1] = __float_as_uint(Bs[(ks * 8 + 4 + g) * 132 + wn + nt * 8 + nrow]);
            }
#pragma unroll
            for (int mt = 0; mt < 4; mt++)
#pragma unroll
                for (int nt = 0; nt < 4; nt++)
                    mma8(c[mt][nt], af[mt], bf[nt]);
        }
    }
}

// ---------------- 2) fused QKV projection ----------------
__global__ __launch_bounds__(256, 2) void qkv_kernel(
    const float* __restrict__ x,
    const float* __restrict__ Wq, const float* __restrict__ bq,
    const float* __restrict__ Wk, const float* __restrict__ bk,
    const float* __restrict__ Wv, const float* __restrict__ bv,
    float* __restrict__ Kout, float* __restrict__ Vout) {
    __shared__ float As[128 * 36];
    __shared__ float Bs[32 * 132];
    const int wsel = blockIdx.z;
    const float* W    = (wsel == 0) ? Wq : (wsel == 1 ? Wk : Wv);
    const float* bias = (wsel == 0) ? bq : (wsel == 1 ? bk : bv);
    const int m0 = blockIdx.y * 128, n0 = blockIdx.x * 128;

    float c[4][4][4];
#pragma unroll
    for (int i = 0; i < 4; i++)
#pragma unroll
        for (int j = 0; j < 4; j++)
#pragma unroll
            for (int k = 0; k < 4; k++) c[i][j][k] = 0.f;

    gemm_core(x, W, m0, n0, c, As, Bs);

    const int t = threadIdx.x, lane = t & 31, wid = t >> 5;
    const int wm = (wid >> 2) * 64, wn = (wid & 3) * 32;
    const int g = lane & 3, rq = lane >> 2;
    const float scale = (wsel == 0) ? 0.08838834764831845f : 1.0f;

#pragma unroll
    for (int mt = 0; mt < 4; mt++) {
#pragma unroll
        for (int nt = 0; nt < 4; nt++) {
            const int col = n0 + wn + nt * 8 + 2 * g;        // global n, even
            float2 bb = *(const float2*)(bias + col);
            const int h = col >> 7, dc = col & 127;
            const int row0 = m0 + wm + mt * 16 + rq;
#pragma unroll
            for (int half = 0; half < 2; half++) {
                const int gr = row0 + half * 8;
                const int b = gr >> 7, tq = gr & 127;
                float2 v;
                v.x = (c[mt][nt][half * 2 + 0] + bb.x) * scale;
                v.y = (c[mt][nt][half * 2 + 1] + bb.y) * scale;
                float* dst;
                if (wsel == 0) {
                    dst = g_Q + ((size_t)((b * 16 + h) * 128 + tq)) * 128 + dc;
                } else {
                    float* base = (wsel == 1) ? Kout : Vout;
                    dst = base + ((size_t)(b * 16 + h) * TT + 2048 + tq) * 128 + dc;
                }
                *(float2*)dst = v;
            }
        }
    }
}

// ---------------- 3) flash attention (tf32 mma), one CTA per (b,h) ----------------
__global__ __launch_bounds__(256, 1) void attn_kernel(const float* __restrict__ Kc,
                                                      const float* __restrict__ Vc) {
    extern __shared__ float sm[];
    float* Qs = sm;                    // [q 128][d 132] tf32 bits
    float* Ks = Qs + 128 * 132;        // [key 128][d 132]
    float* Vs = Ks + 128 * 132;        // [d 128][key 132] (transposed)

    const int bh = blockIdx.x;
    const int t = threadIdx.x, lane = t & 31, wid = t >> 5;
    const int g = lane & 3, rq = lane >> 2;
    const int q0 = wid * 16;
    const int qlow = q0 + rq;

    // load Q (pre-scaled fp32) -> tf32 smem
    const float* Qg = g_Q + (size_t)bh * 128 * 128;
    for (int i = t; i < 4096; i += 256) {
        int r = i >> 5, c4 = (i & 31) * 4;
        float4 v = *(const float4*)(Qg + r * 128 + c4);
        uint4 u = make_uint4(cvt_tf32(v.x), cvt_tf32(v.y), cvt_tf32(v.z), cvt_tf32(v.w));
        *(uint4*)(Qs + r * 132 + c4) = u;
    }

    float m0r = -1e30f, m1r = -1e30f, l0r = 0.f, l1r = 0.f;
    float o[16][4];
#pragma unroll
    for (int i = 0; i < 16; i++)
#pragma unroll
        for (int j = 0; j < 4; j++) o[i][j] = 0.f;

    const float* Kg = Kc + (size_t)bh * TT * 128;
    const float* Vg = Vc + (size_t)bh * TT * 128;

    const u32 lfrag = (((lane & 7) * 132) + ((lane >> 3) & 1) * 4) * 4;  // common x2 lane offset
    const u32 qbase = smem_u32(Qs) +
        (((q0 + (lane & 7) + ((lane >> 3) & 1) * 8) * 132) + (lane >> 4) * 4) * 4;
    const u32 kbase = smem_u32(Ks) + lfrag;
    const u32 vbase = smem_u32(Vs) + lfrag;

    // V loader pattern: per step, lane -> key row, (wid,step) -> d col group
    for (int kt = 0; kt < 17; kt++) {
        __syncthreads();
        // K tile natural [key][d]
        for (int i = t; i < 4096; i += 256) {
            int r = i >> 5, c4 = (i & 31) * 4;
            float4 v = *(const float4*)(Kg + (size_t)(kt * 128 + r) * 128 + c4);
            uint4 u = make_uint4(cvt_tf32(v.x), cvt_tf32(v.y), cvt_tf32(v.z), cvt_tf32(v.w));
            *(uint4*)(Ks + r * 132 + c4) = u;
        }
        // V tile transposed [d][key]: lane = key row => conflict-free STS
#pragma unroll
        for (int s = 0; s < 16; s++) {
            int r = lane + (s & 3) * 32;           // key 0..127
            int c4 = (wid + (s >> 2) * 8) * 4;     // d col group
            float4 v = *(const float4*)(Vg + (size_t)(kt * 128 + r) * 128 + c4);
            Vs[(c4 + 0) * 132 + r] = __uint_as_float(cvt_tf32(v.x));
            Vs[(c4 + 1) * 132 + r] = __uint_as_float(cvt_tf32(v.y));
            Vs[(c4 + 2) * 132 + r] = __uint_as_float(cvt_tf32(v.z));
            Vs[(c4 + 3) * 132 + r] = __uint_as_float(cvt_tf32(v.w));
        }
        __syncthreads();

        // ---- S = Q @ K^T ----
        float s_[16][4];
#pragma unroll
        for (int i = 0; i < 16; i++)
#pragma unroll
            for (int j = 0; j < 4; j++) s_[i][j] = 0.f;

#pragma unroll
        for (int ks = 0; ks < 16; ks++) {
            u32 af[4];
            ldsm_x4(qbase + ks * 32, af[0], af[1], af[2], af[3]);
#pragma unroll
            for (int jt = 0; jt < 16; jt++) {
                u32 bf[2];
                ldsm_x2(kbase + jt * 4224 + ks * 32, bf[0], bf[1]);
                mma8(s_[jt], af, bf);
            }
        }

        // ---- causal mask (only last tile) ----
        if (kt == 16) {
#pragma unroll
            for (int jt = 0; jt < 16; jt++) {
                int kk = jt * 8 + 2 * g;
                if (kk     > qlow)     s_[jt][0] = -1e30f;
                if (kk + 1 > qlow)     s_[jt][1] = -1e30f;
                if (kk     > qlow + 8) s_[jt][2] = -1e30f;
                if (kk + 1 > qlow + 8) s_[jt][3] = -1e30f;
            }
        }

        // ---- online softmax (all state in registers) ----
        float mx0 = -1e30f, mx1 = -1e30f;
#pragma unroll
        for (int jt = 0; jt < 16; jt++) {
            mx0 = fmaxf(mx0, fmaxf(s_[jt][0], s_[jt][1]));
            mx1 = fmaxf(mx1, fmaxf(s_[jt][2], s_[jt][3]));
        }
        mx0 = fmaxf(mx0, __shfl_xor_sync(0xffffffffu, mx0, 1));
        mx0 = fmaxf(mx0, __shfl_xor_sync(0xffffffffu, mx0, 2));
        mx1 = fmaxf(mx1, __shfl_xor_sync(0xffffffffu, mx1, 1));
        mx1 = fmaxf(mx1, __shfl_xor_sync(0xffffffffu, mx1, 2));
        float mn0 = fmaxf(m0r, mx0), mn1 = fmaxf(m1r, mx1);
        float f0 = __expf(m0r - mn0), f1 = __expf(m1r - mn1);
        m0r = mn0; m1r = mn1;

        float ps0 = 0.f, ps1 = 0.f;
#pragma unroll
        for (int jt = 0; jt < 16; jt++) {
            float p0 = __expf(s_[jt][0] - m0r);
            float p1 = __expf(s_[jt][1] - m0r);
            float p2 = __expf(s_[jt][2] - m1r);
            float p3 = __expf(s_[jt][3] - m1r);
            s_[jt][0] = p0; s_[jt][1] = p1; s_[jt][2] = p2; s_[jt][3] = p3;
            ps0 += p0 + p1; ps1 += p2 + p3;
        }
        ps0 += __shfl_xor_sync(0xffffffffu, ps0, 1);
        ps0 += __shfl_xor_sync(0xffffffffu, ps0, 2);
        ps1 += __shfl_xor_sync(0xffffffffu, ps1, 1);
        ps1 += __shfl_xor_sync(0xffffffffu, ps1, 2);
        l0r = l0r * f0 + ps0;
        l1r = l1r * f1 + ps1;

#pragma unroll
        for (int dn = 0; dn < 16; dn++) {
            o[dn][0] *= f0; o[dn][1] *= f0;
            o[dn][2] *= f1; o[dn][3] *= f1;
        }

        // ---- O += P @ V : shfl-permute S-accum -> A-frag, then mma ----
        const int src0 = (lane & ~3) | (g >> 1);
        const int src1 = src0 + 2;
#pragma unroll
        for (int jt = 0; jt < 16; jt++) {
            float t00 = __shfl_sync(0xffffffffu, s_[jt][0], src0);
            float t01 = __shfl_sync(0xffffffffu, s_[jt][1], src0);
            float t10 = __shfl_sync(0xffffffffu, s_[jt][0], src1);
            float t11 = __shfl_sync(0xffffffffu, s_[jt][1], src1);
            float t20 = __shfl_sync(0xffffffffu, s_[jt][2], src0);
            float t21 = __shfl_sync(0xffffffffu, s_[jt][3], src0);
            float t30 = __shfl_sync(0xffffffffu, s_[jt][2], src1);
            float t31 = __shfl_sync(0xffffffffu, s_[jt][3], src1);
            u32 pa[4];
            pa[0] = cvt_tf32((g & 1) ? t01 : t00);   // row low,  col g
            pa[1] = cvt_tf32((g & 1) ? t21 : t20);   // row high, col g
            pa[2] = cvt_tf32((g & 1) ? t11 : t10);   // row low,  col g+4
            pa[3] = cvt_tf32((g & 1) ? t31 : t30);   // row high, col g+4
#pragma unroll
            for (int dn = 0; dn < 16; dn++) {
                u32 bf[2];
                ldsm_x2(vbase + dn * 4224 + jt * 32, bf[0], bf[1]);
                mma8(o[dn], pa, bf);
            }
        }
    }

    // ---- epilogue ----
    const float inv0 = 1.f / l0r, inv1 = 1.f / l1r;
    const int b = bh >> 4, h = bh & 15;
    float* outp = g_attn + ((size_t)(b * 128 + qlow)) * 2048 + h * 128;
#pragma unroll
    for (int dn = 0; dn < 16; dn++) {
        const int col = dn * 8 + 2 * g;
        float2 v0 = make_float2(o[dn][0] * inv0, o[dn][1] * inv0);
        float2 v1 = make_float2(o[dn][2] * inv1, o[dn][3] * inv1);
        *(float2*)(outp + col) = v0;
        *(float2*)(outp + (size_t)8 * 2048 + col) = v1;
    }
}

// ---------------- 4) output projection ----------------
__global__ __launch_bounds__(256, 2) void proj_kernel(const float* __restrict__ Wo,
                                                      const float* __restrict__ bo,
                                                      float* __restrict__ out) {
    __shared__ float As[128 * 36];
    __shared__ float Bs[32 * 132];
    const int m0 = blockIdx.y * 128, n0 = blockIdx.x * 128;

    float c[4][4][4];
#pragma unroll
    for (int i = 0; i < 4; i++)
#pragma unroll
        for (int j = 0; j < 4; j++)
#pragma unroll
            for (int k = 0; k < 4; k++) c[i][j][k] = 0.f;

    gemm_core(g_attn, Wo, m0, n0, c, As, Bs);

    const int t = threadIdx.x, lane = t & 31, wid = t >> 5;
    const int wm = (wid >> 2) * 64, wn = (wid & 3) * 32;
    const int g = lane & 3, rq = lane >> 2;

#pragma unroll
    for (int mt = 0; mt < 4; mt++) {
#pragma unroll
        for (int nt = 0; nt < 4; nt++) {
            const int col = n0 + wn + nt * 8 + 2 * g;
            float2 bb = *(const float2*)(bo + col);
            const int row0 = m0 + wm + mt * 16 + rq;
            float2 v0 = make_float2(c[mt][nt][0] + bb.x, c[mt][nt][1] + bb.y);
            float2 v1 = make_float2(c[mt][nt][2] + bb.x, c[mt][nt][3] + bb.y);
            *(float2*)(out + (size_t)row0 * 2048 + col) = v0;
            *(float2*)(out + (size_t)(row0 + 8) * 2048 + col) = v1;
        }
    }
}

// ---------------- launch ----------------
extern "C" void kernel_launch(void* const* d_in, const int* in_sizes, int n_in,
                              void* d_out, int out_size) {
    const float* x  = (const float*)d_in[0];
    const float* Kp = (const float*)d_in[1];
    const float* Vp = (const float*)d_in[2];
    const float* Wq = (const float*)d_in[3];
    const float* bq = (const float*)d_in[4];
    const float* Wk = (const float*)d_in[5];
    const float* bk = (const float*)d_in[6];
    const float* Wv = (const float*)d_in[7];
    const float* bv = (const float*)d_in[8];
    const float* Wo = (const float*)d_in[9];
    const float* bo = (const float*)d_in[10];

    float* out  = (float*)d_out;
    float* Kout = (float*)d_out + 2097152;                 // B*T_NEW*C
    float* Vout = (float*)d_out + 2097152 + 35651584;      // + B*H*TT*D

    copy_past_kernel<<<32768, 256>>>((const float4*)Kp, (const float4*)Vp,
                                     (float4*)Kout, (float4*)Vout);

    qkv_kernel<<<dim3(16, 8, 3), 256>>>(x, Wq, bq, Wk, bk, Wv, bv, Kout, Vout);

    const int smem_bytes = 3 * 128 * 132 * (int)sizeof(float);   // 202752
    cudaFuncSetAttribute(attn_kernel, cudaFuncAttributeMaxDynamicSharedMemorySize, smem_bytes);
    attn_kernel<<<128, 256, smem_bytes>>>(Kout, Vout);

    proj_kernel<<<dim3(16, 8), 256>>>(Wo, bo, out);
}

// round 4
// speedup vs baseline: 2.9704x; 1.1385x over previous
#include <cuda_runtime.h>
#include <cstdint>

#define TT 2176

typedef unsigned int u32;

// ---------------- device scratch ----------------
__device__ float g_Q[8 * 16 * 128 * 128];      // (B,H,128,128) pre-scaled Q
__device__ float g_attn[8 * 128 * 2048];       // (B,T_NEW,C) attention output

extern __shared__ float sm[];

// ---------------- helpers ----------------
__device__ __forceinline__ u32 cvt_tf32(float f) {
    u32 r; asm("cvt.rna.tf32.f32 %0, %1;" : "=r"(r) : "f"(f)); return r;
}
__device__ __forceinline__ u32 smem_u32(const void* p) {
    return (u32)__cvta_generic_to_shared(p);
}
__device__ __forceinline__ void ldsm_x4(u32 a, u32& r0, u32& r1, u32& r2, u32& r3) {
    asm volatile("ldmatrix.sync.aligned.m8n8.x4.shared.b16 {%0,%1,%2,%3}, [%4];"
                 : "=r"(r0), "=r"(r1), "=r"(r2), "=r"(r3) : "r"(a));
}
__device__ __forceinline__ void ldsm_x2(u32 a, u32& r0, u32& r1) {
    asm volatile("ldmatrix.sync.aligned.m8n8.x2.shared.b16 {%0,%1}, [%2];"
                 : "=r"(r0), "=r"(r1) : "r"(a));
}
__device__ __forceinline__ void mma8(float c[4], const u32 a[4], const u32 b[2]) {
    asm volatile("mma.sync.aligned.m16n8k8.row.col.f32.tf32.tf32.f32 "
                 "{%0,%1,%2,%3}, {%4,%5,%6,%7}, {%8,%9}, {%0,%1,%2,%3};"
                 : "+f"(c[0]), "+f"(c[1]), "+f"(c[2]), "+f"(c[3])
                 : "r"(a[0]), "r"(a[1]), "r"(a[2]), "r"(a[3]), "r"(b[0]), "r"(b[1]));
}

// ---------------- pipelined tf32 GEMM core: 128x128 tile, BK=32, 2-stage ----------------
// As buffers: 2 x [128][36], Bs buffers: 2 x [32][132] (tf32 bits)
__device__ __forceinline__ void sts_tile(const float4 aL[4], const float4 bL[4],
                                         float* As, float* Bs,
                                         int ar, int ac, int br, int bc) {
#pragma unroll
    for (int j = 0; j < 4; j++) {
        uint4 ua = make_uint4(cvt_tf32(aL[j].x), cvt_tf32(aL[j].y),
                              cvt_tf32(aL[j].z), cvt_tf32(aL[j].w));
        *(uint4*)(As + (ar + 32 * j) * 36 + ac) = ua;
        uint4 ub = make_uint4(cvt_tf32(bL[j].x), cvt_tf32(bL[j].y),
                              cvt_tf32(bL[j].z), cvt_tf32(bL[j].w));
        *(uint4*)(Bs + (br + 8 * j) * 132 + bc) = ub;
    }
}

template <bool DOCOPY>
__device__ __forceinline__ void gemm_core(const float* __restrict__ A, const float* __restrict__ W,
                                          int m0, int n0, float c[4][4][4],
                                          float* As0, float* Bs0,
                                          const float4* __restrict__ Kp, const float4* __restrict__ Vp,
                                          float4* __restrict__ Ko, float4* __restrict__ Vo, int cbase) {
    const int t = threadIdx.x, lane = t & 31, wid = t >> 5;
    const int ar = t >> 3, ac = (t & 7) * 4;
    const int br = t >> 5, bc = (t & 31) * 4;
    const int wm = (wid >> 2) * 64, wn = (wid & 3) * 32;
    const int g = lane & 3, nrow = lane >> 2;
    const u32 aoff = (((lane & 7) + ((lane >> 3) & 1) * 8) * 36 + (lane >> 4) * 4) * 4;

    const float* Ap = A + (size_t)(m0 + ar) * 2048 + ac;
    const float* Wp = W + (size_t)br * 2048 + n0 + bc;

    // prologue: load + store k0=0 into buffer 0
    {
        float4 aL[4], bL[4];
#pragma unroll
        for (int j = 0; j < 4; j++) aL[j] = *(const float4*)(Ap + (size_t)(32 * j) * 2048);
#pragma unroll
        for (int j = 0; j < 4; j++) bL[j] = *(const float4*)(Wp + (size_t)(8 * j) * 2048);
        sts_tile(aL, bL, As0, Bs0, ar, ac, br, bc);
    }

    int cur = 0;
    for (int k0 = 0; k0 < 2048; k0 += 32) {
        const bool more = (k0 + 32) < 2048;
        // issue next-tile global loads early (overlap with compute)
        float4 aN[4], bN[4];
        if (more) {
#pragma unroll
            for (int j = 0; j < 4; j++)
                aN[j] = *(const float4*)(Ap + (size_t)(32 * j) * 2048 + k0 + 32);
#pragma unroll
            for (int j = 0; j < 4; j++)
                bN[j] = *(const float4*)(Wp + (size_t)(k0 + 32 + 8 * j) * 2048);
        }
        // folded KV-cache copy: issue loads now, stores after compute
        float4 kc[2], vc[2];
        int cidx[2] = {0x7fffffff, 0x7fffffff};
        if (DOCOPY) {
            const int u0 = (k0 >> 5) * 2;
#pragma unroll
            for (int j = 0; j < 2; j++) {
                int idx = cbase + (u0 + j) * 98304;
                if (idx < 8388608) { cidx[j] = idx; kc[j] = Kp[idx]; vc[j] = Vp[idx]; }
            }
        }
        __syncthreads();
        float* As = As0 + cur * 4608;
        float* Bs = Bs0 + cur * 4224;
        const u32 abase = smem_u32(As) + aoff;
#pragma unroll
        for (int ks = 0; ks < 4; ks++) {
            u32 af[4][4];
#pragma unroll
            for (int mt = 0; mt < 4; mt++)
                ldsm_x4(abase + ((wm + mt * 16) * 36 + ks * 8) * 4,
                        af[mt][0], af[mt][1], af[mt][2], af[mt][3]);
            u32 bf[4][2];
#pragma unroll
            for (int nt = 0; nt < 4; nt++) {
                bf[nt][0] = __float_as_uint(Bs[(ks * 8 + g) * 132 + wn + nt * 8 + nrow]);
                bf[nt][1] = __float_as_uint(Bs[(ks * 8 + 4 + g) * 132 + wn + nt * 8 + nrow]);
            }
#pragma unroll
            for (int mt = 0; mt < 4; mt++)
#pragma unroll
                for (int nt = 0; nt < 4; nt++)
                    mma8(c[mt][nt], af[mt], bf[nt]);
        }
        if (more)
            sts_tile(aN, bN, As0 + (cur ^ 1) * 4608, Bs0 + (cur ^ 1) * 4224, ar, ac, br, bc);
        if (DOCOPY) {
#pragma unroll
            for (int j = 0; j < 2; j++) {
                if (cidx[j] < 8388608) {
                    int bh = cidx[j] >> 16, rem = cidx[j] & 65535;
                    size_t dst = (size_t)bh * 69632 + rem;
                    Ko[dst] = kc[j];
                    Vo[dst] = vc[j];
                }
            }
        }
        cur ^= 1;
    }
}

// ---------------- 2) fused QKV projection + KV-cache copy-through ----------------
__global__ __launch_bounds__(256) void qkv_kernel(
    const float* __restrict__ x,
    const float* __restrict__ Wq, const float* __restrict__ bq,
    const float* __restrict__ Wk, const float* __restrict__ bk,
    const float* __restrict__ Wv, const float* __restrict__ bv,
    const float4* __restrict__ Kp, const float4* __restrict__ Vp,
    float* __restrict__ Kout, float* __restrict__ Vout) {
    float* As0 = sm;
    float* Bs0 = sm + 2 * 4608;
    const int wsel = blockIdx.z;
    const float* W    = (wsel == 0) ? Wq : (wsel == 1 ? Wk : Wv);
    const float* bias = (wsel == 0) ? bq : (wsel == 1 ? bk : bv);
    const int m0 = blockIdx.y * 128, n0 = blockIdx.x * 128;
    const int linblk = blockIdx.x + blockIdx.y * 16 + blockIdx.z * 128;
    const int cbase = linblk * 256 + threadIdx.x;

    float c[4][4][4];
#pragma unroll
    for (int i = 0; i < 4; i++)
#pragma unroll
        for (int j = 0; j < 4; j++)
#pragma unroll
            for (int k = 0; k < 4; k++) c[i][j][k] = 0.f;

    gemm_core<true>(x, W, m0, n0, c, As0, Bs0, Kp, Vp, (float4*)Kout, (float4*)Vout, cbase);

    const int t = threadIdx.x, lane = t & 31, wid = t >> 5;
    const int wm = (wid >> 2) * 64, wn = (wid & 3) * 32;
    const int g = lane & 3, rq = lane >> 2;
    const float scale = (wsel == 0) ? 0.08838834764831845f : 1.0f;

#pragma unroll
    for (int mt = 0; mt < 4; mt++) {
#pragma unroll
        for (int nt = 0; nt < 4; nt++) {
            const int col = n0 + wn + nt * 8 + 2 * g;
            float2 bb = *(const float2*)(bias + col);
            const int h = col >> 7, dc = col & 127;
            const int row0 = m0 + wm + mt * 16 + rq;
#pragma unroll
            for (int half = 0; half < 2; half++) {
                const int gr = row0 + half * 8;
                const int b = gr >> 7, tq = gr & 127;
                float2 v;
                v.x = (c[mt][nt][half * 2 + 0] + bb.x) * scale;
                v.y = (c[mt][nt][half * 2 + 1] + bb.y) * scale;
                float* dst;
                if (wsel == 0) {
                    dst = g_Q + ((size_t)((b * 16 + h) * 128 + tq)) * 128 + dc;
                } else {
                    float* base = (wsel == 1) ? Kout : Vout;
                    dst = base + ((size_t)(b * 16 + h) * TT + 2048 + tq) * 128 + dc;
                }
                *(float2*)dst = v;
            }
        }
    }
}

// ---------------- 3) flash attention (tf32 mma), one CTA per (b,h) ----------------
__global__ __launch_bounds__(256, 1) void attn_kernel(const float* __restrict__ Kc,
                                                      const float* __restrict__ Vc) {
    float* Qs = sm;                    // [q 128][d 132] tf32 bits
    float* Ks = Qs + 128 * 132;        // [key 128][d 132]
    float* Vs = Ks + 128 * 132;        // [d 128][key 132] (transposed)

    const int bh = blockIdx.x;
    const int t = threadIdx.x, lane = t & 31, wid = t >> 5;
    const int g = lane & 3, rq = lane >> 2;
    const int q0 = wid * 16;
    const int qlow = q0 + rq;

    // load Q (pre-scaled fp32) -> tf32 smem (statically unrolled, batched LDGs)
    const float* Qg = g_Q + (size_t)bh * 128 * 128;
#pragma unroll
    for (int s = 0; s < 16; s++) {
        int i = t + s * 256;
        int r = i >> 5, c4 = (i & 31) * 4;
        float4 v = *(const float4*)(Qg + r * 128 + c4);
        uint4 u = make_uint4(cvt_tf32(v.x), cvt_tf32(v.y), cvt_tf32(v.z), cvt_tf32(v.w));
        *(uint4*)(Qs + r * 132 + c4) = u;
    }

    float m0r = -1e30f, m1r = -1e30f, l0r = 0.f, l1r = 0.f;
    float o[16][4];
#pragma unroll
    for (int i = 0; i < 16; i++)
#pragma unroll
        for (int j = 0; j < 4; j++) o[i][j] = 0.f;

    const float* Kg = Kc + (size_t)bh * TT * 128;
    const float* Vg = Vc + (size_t)bh * TT * 128;

    const u32 lfrag = (((lane & 7) * 132) + ((lane >> 3) & 1) * 4) * 4;
    const u32 qbase = smem_u32(Qs) +
        (((q0 + (lane & 7) + ((lane >> 3) & 1) * 8) * 132) + (lane >> 4) * 4) * 4;
    const u32 kbase = smem_u32(Ks) + lfrag;
    const u32 vbase = smem_u32(Vs) + lfrag;

    for (int kt = 0; kt < 17; kt++) {
        __syncthreads();
        // K tile natural [key][d]
#pragma unroll
        for (int s = 0; s < 16; s++) {
            int i = t + s * 256;
            int r = i >> 5, c4 = (i & 31) * 4;
            float4 v = *(const float4*)(Kg + (size_t)(kt * 128 + r) * 128 + c4);
            uint4 u = make_uint4(cvt_tf32(v.x), cvt_tf32(v.y), cvt_tf32(v.z), cvt_tf32(v.w));
            *(uint4*)(Ks + r * 132 + c4) = u;
        }
        // V tile transposed [d][key]
#pragma unroll
        for (int s = 0; s < 16; s++) {
            int r = lane + (s & 3) * 32;
            int c4 = (wid + (s >> 2) * 8) * 4;
            float4 v = *(const float4*)(Vg + (size_t)(kt * 128 + r) * 128 + c4);
            Vs[(c4 + 0) * 132 + r] = __uint_as_float(cvt_tf32(v.x));
            Vs[(c4 + 1) * 132 + r] = __uint_as_float(cvt_tf32(v.y));
            Vs[(c4 + 2) * 132 + r] = __uint_as_float(cvt_tf32(v.z));
            Vs[(c4 + 3) * 132 + r] = __uint_as_float(cvt_tf32(v.w));
        }
        __syncthreads();

        // ---- S = Q @ K^T ----
        float s_[16][4];
#pragma unroll
        for (int i = 0; i < 16; i++)
#pragma unroll
            for (int j = 0; j < 4; j++) s_[i][j] = 0.f;

#pragma unroll
        for (int ks = 0; ks < 16; ks++) {
            u32 af[4];
            ldsm_x4(qbase + ks * 32, af[0], af[1], af[2], af[3]);
#pragma unroll
            for (int jt = 0; jt < 16; jt++) {
                u32 bf[2];
                ldsm_x2(kbase + jt * 4224 + ks * 32, bf[0], bf[1]);
                mma8(s_[jt], af, bf);
            }
        }

        // ---- causal mask (last tile only) ----
        if (kt == 16) {
#pragma unroll
            for (int jt = 0; jt < 16; jt++) {
                int kk = jt * 8 + 2 * g;
                if (kk     > qlow)     s_[jt][0] = -1e30f;
                if (kk + 1 > qlow)     s_[jt][1] = -1e30f;
                if (kk     > qlow + 8) s_[jt][2] = -1e30f;
                if (kk + 1 > qlow + 8) s_[jt][3] = -1e30f;
            }
        }

        // ---- online softmax (register state) ----
        float mx0 = -1e30f, mx1 = -1e30f;
#pragma unroll
        for (int jt = 0; jt < 16; jt++) {
            mx0 = fmaxf(mx0, fmaxf(s_[jt][0], s_[jt][1]));
            mx1 = fmaxf(mx1, fmaxf(s_[jt][2], s_[jt][3]));
        }
        mx0 = fmaxf(mx0, __shfl_xor_sync(0xffffffffu, mx0, 1));
        mx0 = fmaxf(mx0, __shfl_xor_sync(0xffffffffu, mx0, 2));
        mx1 = fmaxf(mx1, __shfl_xor_sync(0xffffffffu, mx1, 1));
        mx1 = fmaxf(mx1, __shfl_xor_sync(0xffffffffu, mx1, 2));
        float mn0 = fmaxf(m0r, mx0), mn1 = fmaxf(m1r, mx1);
        float f0 = __expf(m0r - mn0), f1 = __expf(m1r - mn1);
        m0r = mn0; m1r = mn1;

        float ps0 = 0.f, ps1 = 0.f;
#pragma unroll
        for (int jt = 0; jt < 16; jt++) {
            float p0 = __expf(s_[jt][0] - m0r);
            float p1 = __expf(s_[jt][1] - m0r);
            float p2 = __expf(s_[jt][2] - m1r);
            float p3 = __expf(s_[jt][3] - m1r);
            s_[jt][0] = p0; s_[jt][1] = p1; s_[jt][2] = p2; s_[jt][3] = p3;
            ps0 += p0 + p1; ps1 += p2 + p3;
        }
        ps0 += __shfl_xor_sync(0xffffffffu, ps0, 1);
        ps0 += __shfl_xor_sync(0xffffffffu, ps0, 2);
        ps1 += __shfl_xor_sync(0xffffffffu, ps1, 1);
        ps1 += __shfl_xor_sync(0xffffffffu, ps1, 2);
        l0r = l0r * f0 + ps0;
        l1r = l1r * f1 + ps1;

#pragma unroll
        for (int dn = 0; dn < 16; dn++) {
            o[dn][0] *= f0; o[dn][1] *= f0;
            o[dn][2] *= f1; o[dn][3] *= f1;
        }

        // ---- O += P @ V : shfl-permute S-accum -> A-frag ----
        const int src0 = (lane & ~3) | (g >> 1);
        const int src1 = src0 + 2;
#pragma unroll
        for (int jt = 0; jt < 16; jt++) {
            float t00 = __shfl_sync(0xffffffffu, s_[jt][0], src0);
            float t01 = __shfl_sync(0xffffffffu, s_[jt][1], src0);
            float t10 = __shfl_sync(0xffffffffu, s_[jt][0], src1);
            float t11 = __shfl_sync(0xffffffffu, s_[jt][1], src1);
            float t20 = __shfl_sync(0xffffffffu, s_[jt][2], src0);
            float t21 = __shfl_sync(0xffffffffu, s_[jt][3], src0);
            float t30 = __shfl_sync(0xffffffffu, s_[jt][2], src1);
            float t31 = __shfl_sync(0xffffffffu, s_[jt][3], src1);
            u32 pa[4];
            pa[0] = cvt_tf32((g & 1) ? t01 : t00);
            pa[1] = cvt_tf32((g & 1) ? t21 : t20);
            pa[2] = cvt_tf32((g & 1) ? t11 : t10);
            pa[3] = cvt_tf32((g & 1) ? t31 : t30);
#pragma unroll
            for (int dn = 0; dn < 16; dn++) {
                u32 bf[2];
                ldsm_x2(vbase + dn * 4224 + jt * 32, bf[0], bf[1]);
                mma8(o[dn], pa, bf);
            }
        }
    }

    // ---- epilogue ----
    const float inv0 = 1.f / l0r, inv1 = 1.f / l1r;
    const int b = bh >> 4, h = bh & 15;
    float* outp = g_attn + ((size_t)(b * 128 + qlow)) * 2048 + h * 128;
#pragma unroll
    for (int dn = 0; dn < 16; dn++) {
        const int col = dn * 8 + 2 * g;
        float2 v0 = make_float2(o[dn][0] * inv0, o[dn][1] * inv0);
        float2 v1 = make_float2(o[dn][2] * inv1, o[dn][3] * inv1);
        *(float2*)(outp + col) = v0;
        *(float2*)(outp + (size_t)8 * 2048 + col) = v1;
    }
}

// ---------------- 4) output projection ----------------
__global__ __launch_bounds__(256) void proj_kernel(const float* __restrict__ Wo,
                                                   const float* __restrict__ bo,
                                                   float* __restrict__ out) {
    float* As0 = sm;
    float* Bs0 = sm + 2 * 4608;
    const int m0 = blockIdx.y * 128, n0 = blockIdx.x * 128;

    float c[4][4][4];
#pragma unroll
    for (int i = 0; i < 4; i++)
#pragma unroll
        for (int j = 0; j < 4; j++)
#pragma unroll
            for (int k = 0; k < 4; k++) c[i][j][k] = 0.f;

    gemm_core<false>(g_attn, Wo, m0, n0, c, As0, Bs0, nullptr, nullptr, nullptr, nullptr, 0);

    const int t = threadIdx.x, lane = t & 31, wid = t >> 5;
    const int wm = (wid >> 2) * 64, wn = (wid & 3) * 32;
    const int g = lane & 3, rq = lane >> 2;

#pragma unroll
    for (int mt = 0; mt < 4; mt++) {
#pragma unroll
        for (int nt = 0; nt < 4; nt++) {
            const int col = n0 + wn + nt * 8 + 2 * g;
            float2 bb = *(const float2*)(bo + col);
            const int row0 = m0 + wm + mt * 16 + rq;
            float2 v0 = make_float2(c[mt][nt][0] + bb.x, c[mt][nt][1] + bb.y);
            float2 v1 = make_float2(c[mt][nt][2] + bb.x, c[mt][nt][3] + bb.y);
            *(float2*)(out + (size_t)row0 * 2048 + col) = v0;
            *(float2*)(out + (size_t)(row0 + 8) * 2048 + col) = v1;
        }
    }
}

// ---------------- launch ----------------
extern "C" void kernel_launch(void* const* d_in, const int* in_sizes, int n_in,
                              void* d_out, int out_size) {
    const float* x  = (const float*)d_in[0];
    const float* Kp = (const float*)d_in[1];
    const float* Vp = (const float*)d_in[2];
    const float* Wq = (const float*)d_in[3];
    const float* bq = (const float*)d_in[4];
    const float* Wk = (const float*)d_in[5];
    const float* bk = (const float*)d_in[6];
    const float* Wv = (const float*)d_in[7];
    const float* bv = (const float*)d_in[8];
    const float* Wo = (const float*)d_in[9];
    const float* bo = (const float*)d_in[10];

    float* out  = (float*)d_out;
    float* Kout = (float*)d_out + 2097152;                 // B*T_NEW*C
    float* Vout = (float*)d_out + 2097152 + 35651584;      // + B*H*TT*D

    const int gemm_smem = (2 * 4608 + 2 * 4224) * (int)sizeof(float);   // 70656 B
    cudaFuncSetAttribute(qkv_kernel, cudaFuncAttributeMaxDynamicSharedMemorySize, gemm_smem);
    cudaFuncSetAttribute(proj_kernel, cudaFuncAttributeMaxDynamicSharedMemorySize, gemm_smem);

    // 1+2) fused QKV projection with KV-cache copy-through folded in
    qkv_kernel<<<dim3(16, 8, 3), 256, gemm_smem>>>(x, Wq, bq, Wk, bk, Wv, bv,
                                                   (const float4*)Kp, (const float4*)Vp,
                                                   Kout, Vout);

    // 3) attention
    const int attn_smem = 3 * 128 * 132 * (int)sizeof(float);   // 202752 B
    cudaFuncSetAttribute(attn_kernel, cudaFuncAttributeMaxDynamicSharedMemorySize, attn_smem);
    attn_kernel<<<128, 256, attn_smem>>>(Kout, Vout);

    // 4) output projection
    proj_kernel<<<dim3(16, 8), 256, gemm_smem>>>(Wo, bo, out);
}